// round 6
// baseline (speedup 1.0000x reference)
#include <cuda_runtime.h>
#include <cuda_fp16.h>
#include <math.h>

#define SVAL 64
#define DIM 256
#define VOXELS (DIM * DIM * DIM)

// Scratch: x-pair-duplicated half volume in 2x2x2 brick layout.
// Entry (x,y,z) = half2(v[z,y,x], v[z,y,min(x+1,255)]), 4B.
// Brick = 2x2x2 entries = 32B = exactly one L2/L1 sector.
// idx = brick(x>>1,y>>1,z>>1)*8 + ((z&1)<<2 | (y&1)<<1 | (x&1))
// Total 67MB -> L2-resident (126MB). Footprint cap is load-bearing (R4 lesson).
__device__ __half2 g_dup[VOXELS];

__device__ __forceinline__ int brick_idx(int x, int y, int z)
{
    return (((((z >> 1) << 7) | (y >> 1)) << 7 | (x >> 1)) << 3)
         | ((z & 1) << 2) | ((y & 1) << 1) | (x & 1);
}

// One block per (yb, zb) brick-row: handles 4 volume rows (2y x 2z) across full x.
__global__ __launch_bounds__(128) void build_dup_kernel(const float* __restrict__ vol)
{
    __shared__ float sm[4][DIM];
    const int bid = blockIdx.x;          // 16384
    const int tid = threadIdx.x;         // 128
    const int zb = bid >> 7;
    const int yb = bid & 127;

#pragma unroll
    for (int r = 0; r < 4; r++) {
        const int z = 2 * zb + (r >> 1);
        const int y = 2 * yb + (r & 1);
        const float* row = vol + ((size_t)z * DIM + y) * DIM;
        sm[r][tid]       = __ldg(row + tid);
        sm[r][tid + 128] = __ldg(row + tid + 128);
    }
    __syncthreads();

    const int x0 = 2 * tid;
    const int x1 = 2 * tid + 1;
    const int x2 = min(2 * tid + 2, DIM - 1);

    unsigned u[8];
#pragma unroll
    for (int r = 0; r < 4; r++) {
        __half2 e0 = __floats2half2_rn(sm[r][x0], sm[r][x1]);
        __half2 e1 = __floats2half2_rn(sm[r][x1], sm[r][x2]);
        // entry offset = (zbit<<2)|(ybit<<1)|xbit = r*2 + xbit
        u[2 * r + 0] = *(unsigned*)&e0;
        u[2 * r + 1] = *(unsigned*)&e1;
    }

    // brick (tid, yb, zb): 8 entries = 32B, coalesced across threads
    uint4* out = (uint4*)(g_dup + (((size_t)(zb * 128 + yb) * 128) << 3));
    out[2 * tid + 0] = make_uint4(u[0], u[1], u[2], u[3]);
    out[2 * tid + 1] = make_uint4(u[4], u[5], u[6], u[7]);
}

__global__ __launch_bounds__(256) void psf_sample_kernel(
    const float* __restrict__ sampleGrid, // [N,3]
    const float* __restrict__ ax,         // [N,6]
    const float* __restrict__ bound,      // [N,2,3]
    const float* __restrict__ invcov,     // [3,3]
    const float* __restrict__ xyz_psf,    // [N,S,3]
    float* __restrict__ out,              // [N]
    int N)
{
    const int warps_per_block = blockDim.x >> 5;
    const int n = blockIdx.x * warps_per_block + (threadIdx.x >> 5);
    if (n >= N) return;
    const int lane = threadIdx.x & 31;

    // ---- per-ray uniform setup (broadcast loads) ----
    const float vx = __ldg(ax + (size_t)n * 6 + 0);
    const float vy = __ldg(ax + (size_t)n * 6 + 1);
    const float vz = __ldg(ax + (size_t)n * 6 + 2);
    const float tx = __ldg(ax + (size_t)n * 6 + 3);
    const float ty = __ldg(ax + (size_t)n * 6 + 4);
    const float tz = __ldg(ax + (size_t)n * 6 + 5);

    const float theta = sqrtf(vx * vx + vy * vy + vz * vz);
    const float invt = 1.0f / fmaxf(theta, 1e-12f);
    const float kx = vx * invt, ky = vy * invt, kz = vz * invt;
    const float st = sinf(theta);
    const float ct = cosf(theta);
    const float oc = 1.0f - ct;

    const float r00 = 1.0f - oc * (ky * ky + kz * kz);
    const float r01 = -st * kz + oc * kx * ky;
    const float r02 =  st * ky + oc * kx * kz;
    const float r10 =  st * kz + oc * kx * ky;
    const float r11 = 1.0f - oc * (kx * kx + kz * kz);
    const float r12 = -st * kx + oc * ky * kz;
    const float r20 = -st * ky + oc * kx * kz;
    const float r21 =  st * kx + oc * ky * kz;
    const float r22 = 1.0f - oc * (kx * kx + ky * ky);

    const float sgx = __ldg(sampleGrid + (size_t)n * 3 + 0);
    const float sgy = __ldg(sampleGrid + (size_t)n * 3 + 1);
    const float sgz = __ldg(sampleGrid + (size_t)n * 3 + 2);

    const float px = sgx + tx, py = sgy + ty, pz = sgz + tz;
    const float cx = r00 * px + r01 * py + r02 * pz;
    const float cy = r10 * px + r11 * py + r12 * pz;
    const float cz = r20 * px + r21 * py + r22 * pz;

    const float hx = 0.5f * (__ldg(bound + (size_t)n * 6 + 3) - __ldg(bound + (size_t)n * 6 + 0));
    const float hy = 0.5f * (__ldg(bound + (size_t)n * 6 + 4) - __ldg(bound + (size_t)n * 6 + 1));
    const float hz = 0.5f * (__ldg(bound + (size_t)n * 6 + 5) - __ldg(bound + (size_t)n * 6 + 2));

    const float c00 = __ldg(invcov + 0), c01 = __ldg(invcov + 1), c02 = __ldg(invcov + 2);
    const float c10 = __ldg(invcov + 3), c11 = __ldg(invcov + 4), c12 = __ldg(invcov + 5);
    const float c20 = __ldg(invcov + 6), c21 = __ldg(invcov + 7), c22 = __ldg(invcov + 8);

    float sum_vw = 0.0f;
    float sum_w = 0.0f;

    const float* psf_base = xyz_psf + (size_t)n * SVAL * 3;
    const float SCL = 256.0f / 255.0f;   // pix = world*SCL - 0.5

#pragma unroll
    for (int rep = 0; rep < 2; rep++) {
        const int s = lane + rep * 32;
        // streaming hint: one-shot 100MB stream must not evict the dup volume
        const float ex = __ldcs(psf_base + s * 3 + 0) * hx;
        const float ey = __ldcs(psf_base + s * 3 + 1) * hy;
        const float ez = __ldcs(psf_base + s * 3 + 2) * hz;

        const float pixx = fmaf(cx + ex, SCL, -0.5f);
        const float pixy = fmaf(cy + ey, SCL, -0.5f);
        const float pixz = fmaf(cz + ez, SCL, -0.5f);

        const float fx0 = floorf(pixx), fy0 = floorf(pixy), fz0 = floorf(pixz);
        const int x0 = (int)fx0, y0 = (int)fy0, z0 = (int)fz0;
        const float fx = pixx - fx0, fy = pixy - fy0, fz = pixz - fz0;

        const bool xin = (x0 >= 0);
        const bool vx0 = xin & (x0 < DIM);
        const bool vx1 = (x0 >= -1) & (x0 < DIM - 1);
        const bool vy0 = (y0 >= 0) & (y0 < DIM);
        const bool vy1 = (y0 >= -1) & (y0 < DIM - 1);
        const bool vz0 = (z0 >= 0) & (z0 < DIM);
        const bool vz1 = (z0 >= -1) & (z0 < DIM - 1);

        const int xc0 = min(max(x0, 0), DIM - 1);
        const int yc0 = min(max(y0, 0), DIM - 1);
        const int yc1 = min(max(y0 + 1, 0), DIM - 1);
        const int zc0 = min(max(z0, 0), DIM - 1);
        const int zc1 = min(max(z0 + 1, 0), DIM - 1);

        const bool rv00 = vz0 & vy0;
        const bool rv01 = vz0 & vy1;
        const bool rv10 = vz1 & vy0;
        const bool rv11 = vz1 & vy1;

        const int b00 = brick_idx(xc0, yc0, zc0);
        const int b01 = brick_idx(xc0, yc1, zc0);
        const int b10 = brick_idx(xc0, yc0, zc1);
        const int b11 = brick_idx(xc0, yc1, zc1);

        const __half2 HZ = __float2half2_rn(0.0f);
        const __half2 d00 = rv00 ? __ldg(g_dup + b00) : HZ;
        const __half2 d01 = rv01 ? __ldg(g_dup + b01) : HZ;
        const __half2 d10 = rv10 ? __ldg(g_dup + b10) : HZ;
        const __half2 d11 = rv11 ? __ldg(g_dup + b11) : HZ;

        const float2 f00 = __half22float2(d00);
        const float2 f01 = __half22float2(d01);
        const float2 f10 = __half22float2(d10);
        const float2 f11 = __half22float2(d11);

        const float v000 = vx0 ? f00.x : 0.f;
        const float v001 = vx1 ? (xin ? f00.y : f00.x) : 0.f;
        const float v010 = vx0 ? f01.x : 0.f;
        const float v011 = vx1 ? (xin ? f01.y : f01.x) : 0.f;
        const float v100 = vx0 ? f10.x : 0.f;
        const float v101 = vx1 ? (xin ? f10.y : f10.x) : 0.f;
        const float v110 = vx0 ? f11.x : 0.f;
        const float v111 = vx1 ? (xin ? f11.y : f11.x) : 0.f;

        const float wx0 = 1.0f - fx, wy0 = 1.0f - fy, wz0 = 1.0f - fz;

        const float vz0p =
            wy0 * fmaf(wx0, v000, fx * v001) + fy * fmaf(wx0, v010, fx * v011);
        const float vz1p =
            wy0 * fmaf(wx0, v100, fx * v101) + fy * fmaf(wx0, v110, fx * v111);
        const float val = fmaf(wz0, vz0p, fz * vz1p);

        const float q =
            ex * (c00 * ex + c01 * ey + c02 * ez) +
            ey * (c10 * ex + c11 * ey + c12 * ez) +
            ez * (c20 * ex + c21 * ey + c22 * ez);
        const float w = __expf(-0.5f * q);

        sum_vw = fmaf(w, val, sum_vw);
        sum_w += w;
    }

#pragma unroll
    for (int off = 16; off > 0; off >>= 1) {
        sum_vw += __shfl_xor_sync(0xFFFFFFFFu, sum_vw, off);
        sum_w  += __shfl_xor_sync(0xFFFFFFFFu, sum_w, off);
    }

    if (lane == 0) {
        out[n] = sum_vw / sum_w;
    }
}

extern "C" void kernel_launch(void* const* d_in, const int* in_sizes, int n_in,
                              void* d_out, int out_size)
{
    const float* x          = (const float*)d_in[0];
    const float* sampleGrid = (const float*)d_in[1];
    const float* ax         = (const float*)d_in[2];
    const float* bound      = (const float*)d_in[3];
    const float* invcov     = (const float*)d_in[4];
    const float* xyz_psf    = (const float*)d_in[5];
    float* out = (float*)d_out;

    const int N = in_sizes[1] / 3;

    // Pre-pass: build bricked x-dup half2 volume (67MB, L2-resident)
    build_dup_kernel<<<128 * 128, 128>>>(x);

    // Main kernel: warp per ray
    {
        const int threads = 256;
        const int warps_per_block = threads / 32;
        const int blocks = (N + warps_per_block - 1) / warps_per_block;
        psf_sample_kernel<<<blocks, threads>>>(sampleGrid, ax, bound, invcov,
                                               xyz_psf, out, N);
    }
}

// round 7
// speedup vs baseline: 1.2614x; 1.2614x over previous
#include <cuda_runtime.h>
#include <cuda_fp16.h>
#include <math.h>

#define SVAL 64
#define DIM 256
#define VOXELS (DIM * DIM * DIM)

// Scratch: pair-duplicated half volume. dup[i] = (vol[i], vol[i+1 within row]).
// 4B/voxel = 67MB -> fits in L2 (126MB). L2 residency is load-bearing (R4 lesson).
__device__ __half2 g_dup[VOXELS];

__global__ __launch_bounds__(256) void build_dup_kernel(const float* __restrict__ vol)
{
    const int t = blockIdx.x * blockDim.x + threadIdx.x; // one thread per 4 voxels
    if (t >= VOXELS / 4) return;
    const int base = t * 4;
    const float4 v = __ldg((const float4*)(vol + base));
    const int x = base & (DIM - 1);
    const float nxt = (x == DIM - 4) ? v.w : __ldg(vol + base + 4);

    __half2 h0 = __floats2half2_rn(v.x, v.y);
    __half2 h1 = __floats2half2_rn(v.y, v.z);
    __half2 h2 = __floats2half2_rn(v.z, v.w);
    __half2 h3 = __floats2half2_rn(v.w, nxt);

    uint4 p;
    p.x = *(unsigned int*)&h0;
    p.y = *(unsigned int*)&h1;
    p.z = *(unsigned int*)&h2;
    p.w = *(unsigned int*)&h3;
    ((uint4*)g_dup)[t] = p;
}

__global__ __launch_bounds__(256) void psf_sample_kernel(
    const float* __restrict__ sampleGrid, // [N,3]
    const float* __restrict__ ax,         // [N,6]
    const float* __restrict__ bound,      // [N,2,3]
    const float* __restrict__ invcov,     // [3,3]
    const float* __restrict__ xyz_psf,    // [N,S,3]
    float* __restrict__ out,              // [N]
    int N)
{
    const int warps_per_block = blockDim.x >> 5;
    const int n = blockIdx.x * warps_per_block + (threadIdx.x >> 5);
    if (n >= N) return;
    const int lane = threadIdx.x & 31;

    // ---- per-ray uniform setup (broadcast loads) ----
    const float vx = __ldg(ax + (size_t)n * 6 + 0);
    const float vy = __ldg(ax + (size_t)n * 6 + 1);
    const float vz = __ldg(ax + (size_t)n * 6 + 2);
    const float tx = __ldg(ax + (size_t)n * 6 + 3);
    const float ty = __ldg(ax + (size_t)n * 6 + 4);
    const float tz = __ldg(ax + (size_t)n * 6 + 5);

    const float theta = sqrtf(vx * vx + vy * vy + vz * vz);
    const float invt = 1.0f / fmaxf(theta, 1e-12f);
    const float kx = vx * invt, ky = vy * invt, kz = vz * invt;
    const float st = sinf(theta);
    const float ct = cosf(theta);
    const float oc = 1.0f - ct;

    const float r00 = 1.0f - oc * (ky * ky + kz * kz);
    const float r01 = -st * kz + oc * kx * ky;
    const float r02 =  st * ky + oc * kx * kz;
    const float r10 =  st * kz + oc * kx * ky;
    const float r11 = 1.0f - oc * (kx * kx + kz * kz);
    const float r12 = -st * kx + oc * ky * kz;
    const float r20 = -st * ky + oc * kx * kz;
    const float r21 =  st * kx + oc * ky * kz;
    const float r22 = 1.0f - oc * (kx * kx + ky * ky);

    const float sgx = __ldg(sampleGrid + (size_t)n * 3 + 0);
    const float sgy = __ldg(sampleGrid + (size_t)n * 3 + 1);
    const float sgz = __ldg(sampleGrid + (size_t)n * 3 + 2);

    const float px = sgx + tx, py = sgy + ty, pz = sgz + tz;
    const float cx = r00 * px + r01 * py + r02 * pz;
    const float cy = r10 * px + r11 * py + r12 * pz;
    const float cz = r20 * px + r21 * py + r22 * pz;

    const float hx = 0.5f * (__ldg(bound + (size_t)n * 6 + 3) - __ldg(bound + (size_t)n * 6 + 0));
    const float hy = 0.5f * (__ldg(bound + (size_t)n * 6 + 4) - __ldg(bound + (size_t)n * 6 + 1));
    const float hz = 0.5f * (__ldg(bound + (size_t)n * 6 + 5) - __ldg(bound + (size_t)n * 6 + 2));

    const float c00 = __ldg(invcov + 0), c01 = __ldg(invcov + 1), c02 = __ldg(invcov + 2);
    const float c10 = __ldg(invcov + 3), c11 = __ldg(invcov + 4), c12 = __ldg(invcov + 5);
    const float c20 = __ldg(invcov + 6), c21 = __ldg(invcov + 7), c22 = __ldg(invcov + 8);

    float sum_vw = 0.0f;
    float sum_w = 0.0f;

    const float* psf_base = xyz_psf + (size_t)n * SVAL * 3;
    const float SCL = 256.0f / 255.0f;   // pix = world*SCL - 0.5

#pragma unroll
    for (int rep = 0; rep < 2; rep++) {
        const int s = lane + rep * 32;
        const float ex = __ldg(psf_base + s * 3 + 0) * hx;
        const float ey = __ldg(psf_base + s * 3 + 1) * hy;
        const float ez = __ldg(psf_base + s * 3 + 2) * hz;

        const float pixx = fmaf(cx + ex, SCL, -0.5f);
        const float pixy = fmaf(cy + ey, SCL, -0.5f);
        const float pixz = fmaf(cz + ez, SCL, -0.5f);

        const float fx0 = floorf(pixx), fy0 = floorf(pixy), fz0 = floorf(pixz);
        const int x0 = (int)fx0, y0 = (int)fy0, z0 = (int)fz0;
        const float fx = pixx - fx0, fy = pixy - fy0, fz = pixz - fz0;

        float val;

        // interior: both taps valid in every dim, no masking needed
        const bool interior = ((unsigned)x0 < 255u) & ((unsigned)y0 < 255u) & ((unsigned)z0 < 255u);

        if (__all_sync(0xFFFFFFFFu, interior)) {
            // ---- fast path: single base index, immediate-offset LDGs ----
            const int b = (z0 * DIM + y0) * DIM + x0;
            const float2 f00 = __half22float2(__ldg(g_dup + b));
            const float2 f01 = __half22float2(__ldg(g_dup + b + DIM));
            const float2 f10 = __half22float2(__ldg(g_dup + b + DIM * DIM));
            const float2 f11 = __half22float2(__ldg(g_dup + b + DIM * DIM + DIM));

            const float wy0 = 1.0f - fy, wz0 = 1.0f - fz;
            const float xi00 = fmaf(fx, f00.y - f00.x, f00.x);
            const float xi01 = fmaf(fx, f01.y - f01.x, f01.x);
            const float xi10 = fmaf(fx, f10.y - f10.x, f10.x);
            const float xi11 = fmaf(fx, f11.y - f11.x, f11.x);
            const float z0p = fmaf(fy, xi01, wy0 * xi00 - fy * 0.0f); // wy0*xi00 + fy*xi01
            const float z1p = wy0 * xi10 + fy * xi11;
            val = fmaf(wz0, wy0 * xi00 + fy * xi01, fz * z1p);
            (void)z0p;
        } else {
            // ---- masked path (border warps only) ----
            const bool xin = (x0 >= 0);
            const bool vx0 = xin & (x0 < DIM);
            const bool vx1 = (x0 >= -1) & (x0 < DIM - 1);
            const bool vy0 = (y0 >= 0) & (y0 < DIM);
            const bool vy1 = (y0 >= -1) & (y0 < DIM - 1);
            const bool vz0 = (z0 >= 0) & (z0 < DIM);
            const bool vz1 = (z0 >= -1) & (z0 < DIM - 1);

            const int xc0 = min(max(x0, 0), DIM - 1);
            const int yc0 = min(max(y0, 0), DIM - 1);
            const int yc1 = min(max(y0 + 1, 0), DIM - 1);
            const int zc0 = min(max(z0, 0), DIM - 1);
            const int zc1 = min(max(z0 + 1, 0), DIM - 1);

            const bool rv00 = vz0 & vy0;
            const bool rv01 = vz0 & vy1;
            const bool rv10 = vz1 & vy0;
            const bool rv11 = vz1 & vy1;

            const int b00 = (zc0 * DIM + yc0) * DIM + xc0;
            const int b01 = (zc0 * DIM + yc1) * DIM + xc0;
            const int b10 = (zc1 * DIM + yc0) * DIM + xc0;
            const int b11 = (zc1 * DIM + yc1) * DIM + xc0;

            const __half2 HZ = __float2half2_rn(0.0f);
            const __half2 d00 = rv00 ? __ldg(g_dup + b00) : HZ;
            const __half2 d01 = rv01 ? __ldg(g_dup + b01) : HZ;
            const __half2 d10 = rv10 ? __ldg(g_dup + b10) : HZ;
            const __half2 d11 = rv11 ? __ldg(g_dup + b11) : HZ;

            const float2 f00 = __half22float2(d00);
            const float2 f01 = __half22float2(d01);
            const float2 f10 = __half22float2(d10);
            const float2 f11 = __half22float2(d11);

            const float v000 = vx0 ? f00.x : 0.f;
            const float v001 = vx1 ? (xin ? f00.y : f00.x) : 0.f;
            const float v010 = vx0 ? f01.x : 0.f;
            const float v011 = vx1 ? (xin ? f01.y : f01.x) : 0.f;
            const float v100 = vx0 ? f10.x : 0.f;
            const float v101 = vx1 ? (xin ? f10.y : f10.x) : 0.f;
            const float v110 = vx0 ? f11.x : 0.f;
            const float v111 = vx1 ? (xin ? f11.y : f11.x) : 0.f;

            const float wx0 = 1.0f - fx, wy0 = 1.0f - fy, wz0 = 1.0f - fz;

            const float vz0p =
                wy0 * fmaf(wx0, v000, fx * v001) + fy * fmaf(wx0, v010, fx * v011);
            const float vz1p =
                wy0 * fmaf(wx0, v100, fx * v101) + fy * fmaf(wx0, v110, fx * v111);
            val = fmaf(wz0, vz0p, fz * vz1p);
        }

        const float q =
            ex * (c00 * ex + c01 * ey + c02 * ez) +
            ey * (c10 * ex + c11 * ey + c12 * ez) +
            ez * (c20 * ex + c21 * ey + c22 * ez);
        const float w = __expf(-0.5f * q);

        sum_vw = fmaf(w, val, sum_vw);
        sum_w += w;
    }

#pragma unroll
    for (int off = 16; off > 0; off >>= 1) {
        sum_vw += __shfl_xor_sync(0xFFFFFFFFu, sum_vw, off);
        sum_w  += __shfl_xor_sync(0xFFFFFFFFu, sum_w, off);
    }

    if (lane == 0) {
        out[n] = sum_vw / sum_w;
    }
}

extern "C" void kernel_launch(void* const* d_in, const int* in_sizes, int n_in,
                              void* d_out, int out_size)
{
    const float* x          = (const float*)d_in[0];
    const float* sampleGrid = (const float*)d_in[1];
    const float* ax         = (const float*)d_in[2];
    const float* bound      = (const float*)d_in[3];
    const float* invcov     = (const float*)d_in[4];
    const float* xyz_psf    = (const float*)d_in[5];
    float* out = (float*)d_out;

    const int N = in_sizes[1] / 3;

    // Pre-pass: build pair-duplicated half2 volume (67MB, L2-resident)
    {
        const int threads = 256;
        const int work = VOXELS / 4;
        const int blocks = (work + threads - 1) / threads;
        build_dup_kernel<<<blocks, threads>>>(x);
    }

    // Main kernel: warp per ray
    {
        const int threads = 256;
        const int warps_per_block = threads / 32;
        const int blocks = (N + warps_per_block - 1) / warps_per_block;
        psf_sample_kernel<<<blocks, threads>>>(sampleGrid, ax, bound, invcov,
                                               xyz_psf, out, N);
    }
}